// round 5
// baseline (speedup 1.0000x reference)
#include <cuda_runtime.h>
#include <math.h>

#define NN 50000
#define EE 800000
#define C 64
#define EPSF 1.000001f

// Scratch (device globals: no allocation allowed anywhere).
// __align__(16) so float4 loads are legal.
__device__ __align__(16) float g_xm_l[NN * C];
__device__ __align__(16) float g_xm_u[NN * C];
__device__ float g_ss[4 * NN];   // [s_src_l | s_tgt_l | s_src_u | s_tgt_u]

// ---------------------------------------------------------------------------
// Kernel A: three fused GEMMs. Block = 256 threads = 4 rows x 64 cols.
// xm_l, xm_u -> device-global scratch; (x @ w_lin) * EPS -> d_out (overwrite).
// ---------------------------------------------------------------------------
__global__ void gemm3_kernel(const float* __restrict__ x,
                             const float* __restrict__ w_l,
                             const float* __restrict__ w_u,
                             const float* __restrict__ w_lin,
                             float* __restrict__ out) {
    __shared__ float xs[4][C];
    int r_loc = threadIdx.x >> 6;      // 0..3
    int c = threadIdx.x & 63;          // 0..63
    int row = blockIdx.x * 4 + r_loc;

    if (row < NN) xs[r_loc][c] = x[(size_t)row * C + c];
    __syncthreads();
    if (row >= NN) return;

    float al = 0.f, au = 0.f, aw = 0.f;
#pragma unroll
    for (int k = 0; k < C; k++) {
        float xv = xs[r_loc][k];
        al = fmaf(xv, w_l[k * C + c], al);
        au = fmaf(xv, w_u[k * C + c], au);
        aw = fmaf(xv, w_lin[k * C + c], aw);
    }
    size_t o = (size_t)row * C + c;
    g_xm_l[o] = al;
    g_xm_u[o] = au;
    out[o] = aw * EPSF;
}

// ---------------------------------------------------------------------------
// Kernel B: per-node attention scalars. One warp per node.
// s_src = xm @ a[:64], s_tgt = xm @ a[64:], for lower and upper branches.
// ---------------------------------------------------------------------------
__global__ void scalars_kernel(const float* __restrict__ a_l,
                               const float* __restrict__ a_u) {
    int warp = (blockIdx.x * blockDim.x + threadIdx.x) >> 5;
    int lane = threadIdx.x & 31;
    if (warp >= NN) return;
    size_t base = (size_t)warp * C;

    float xl0 = g_xm_l[base + lane];
    float xl1 = g_xm_l[base + 32 + lane];
    float xu0 = g_xm_u[base + lane];
    float xu1 = g_xm_u[base + 32 + lane];

    float ssl = xl0 * a_l[lane]      + xl1 * a_l[lane + 32];
    float stl = xl0 * a_l[lane + 64] + xl1 * a_l[lane + 96];
    float ssu = xu0 * a_u[lane]      + xu1 * a_u[lane + 32];
    float stu = xu0 * a_u[lane + 64] + xu1 * a_u[lane + 96];

#pragma unroll
    for (int off = 16; off > 0; off >>= 1) {
        ssl += __shfl_xor_sync(0xFFFFFFFFu, ssl, off);
        stl += __shfl_xor_sync(0xFFFFFFFFu, stl, off);
        ssu += __shfl_xor_sync(0xFFFFFFFFu, ssu, off);
        stu += __shfl_xor_sync(0xFFFFFFFFu, stu, off);
    }
    if (lane == 0) {
        g_ss[warp]          = ssl;
        g_ss[NN + warp]     = stl;
        g_ss[2 * NN + warp] = ssu;
        g_ss[3 * NN + warp] = stu;
    }
}

// ---------------------------------------------------------------------------
// Kernel C: edge scatter. 16 threads per edge; float4 gather + 4x atomicAdd.
// alpha = elu(s_src[j] + s_tgt[i]) * val;  out[i] += alpha * xm[j]
// idx: int32 (2, E) row-major -> [0..E) = targets i, [E..2E) = sources j.
// LOWER=1 -> g_xm_l / g_ss[0..], LOWER=0 -> g_xm_u / g_ss[2N..].
// ---------------------------------------------------------------------------
template <int LOWER>
__global__ void edge_kernel(const int* __restrict__ idx,
                            const float* __restrict__ vals,
                            float* __restrict__ out) {
    int t = blockIdx.x * blockDim.x + threadIdx.x;
    int e = t >> 4;
    if (e >= EE) return;
    int part = (t & 15) * 4;

    const float* xm    = LOWER ? g_xm_l : g_xm_u;
    const float* s_src = LOWER ? g_ss          : g_ss + 2 * NN;
    const float* s_tgt = LOWER ? g_ss + NN     : g_ss + 3 * NN;

    int i = idx[e];
    int j = idx[EE + e];
    float s = s_src[j] + s_tgt[i];
    float el = (s > 0.f) ? s : expm1f(s);
    float alpha = el * vals[e];

    float4 m = *reinterpret_cast<const float4*>(xm + (size_t)j * C + part);
    float* p = out + (size_t)i * C + part;
    atomicAdd(p + 0, alpha * m.x);
    atomicAdd(p + 1, alpha * m.y);
    atomicAdd(p + 2, alpha * m.z);
    atomicAdd(p + 3, alpha * m.w);
}

// ---------------------------------------------------------------------------
// Kernel D: in-place ReLU on d_out.
// ---------------------------------------------------------------------------
__global__ void relu_kernel(float* __restrict__ out) {
    int t = blockIdx.x * blockDim.x + threadIdx.x;
    if (t >= NN * C / 4) return;
    float4* p = reinterpret_cast<float4*>(out) + t;
    float4 v = *p;
    v.x = fmaxf(v.x, 0.f);
    v.y = fmaxf(v.y, 0.f);
    v.z = fmaxf(v.z, 0.f);
    v.w = fmaxf(v.w, 0.f);
    *p = v;
}

// ---------------------------------------------------------------------------
extern "C" void kernel_launch(void* const* d_in, const int* in_sizes, int n_in,
                              void* d_out, int out_size) {
    const float* x      = (const float*)d_in[0];
    const int*   l_idx  = (const int*)d_in[1];
    const float* l_vals = (const float*)d_in[2];
    const int*   u_idx  = (const int*)d_in[3];
    const float* u_vals = (const float*)d_in[4];
    const float* w_l    = (const float*)d_in[5];
    const float* a_l    = (const float*)d_in[6];
    const float* w_u    = (const float*)d_in[7];
    const float* a_u    = (const float*)d_in[8];
    const float* w_lin  = (const float*)d_in[9];
    float* out = (float*)d_out;

    // A: GEMMs (+ w_x -> d_out overwrite)
    gemm3_kernel<<<(NN + 3) / 4, 256>>>(x, w_l, w_u, w_lin, out);

    // B: attention scalars (warp per node, 8 warps/block)
    scalars_kernel<<<(NN + 7) / 8, 256>>>(a_l, a_u);

    // C: edge scatters (16 threads/edge)
    int eblocks = (EE * 16) / 256;  // 800000*16/256 = 50000, exact
    edge_kernel<1><<<eblocks, 256>>>(l_idx, l_vals, out);
    edge_kernel<0><<<eblocks, 256>>>(u_idx, u_vals, out);

    // D: ReLU in place
    relu_kernel<<<(NN * C / 4 + 255) / 256, 256>>>(out);
}

// round 6
// speedup vs baseline: 1.5531x; 1.5531x over previous
#include <cuda_runtime.h>
#include <math.h>

#define NN 50000
#define EE 800000
#define C 64
#define EPSF 1.000001f

// Scratch (device globals: no allocation allowed anywhere).
__device__ __align__(16) float g_xm_l[NN * C];
__device__ __align__(16) float g_xm_u[NN * C];
__device__ float g_ss[4 * NN];   // [s_src_l | s_tgt_l | s_src_u | s_tgt_u]

// ---------------------------------------------------------------------------
// Kernel A: three fused GEMMs. Block = 256 threads = 4 rows x 64 cols.
// xm_l, xm_u -> device-global scratch; (x @ w_lin) * EPS -> d_out (overwrite).
// ---------------------------------------------------------------------------
__global__ void gemm3_kernel(const float* __restrict__ x,
                             const float* __restrict__ w_l,
                             const float* __restrict__ w_u,
                             const float* __restrict__ w_lin,
                             float* __restrict__ out) {
    __shared__ float xs[4][C];
    int r_loc = threadIdx.x >> 6;      // 0..3
    int c = threadIdx.x & 63;          // 0..63
    int row = blockIdx.x * 4 + r_loc;

    if (row < NN) xs[r_loc][c] = x[(size_t)row * C + c];
    __syncthreads();
    if (row >= NN) return;

    float al = 0.f, au = 0.f, aw = 0.f;
#pragma unroll
    for (int k = 0; k < C; k++) {
        float xv = xs[r_loc][k];
        al = fmaf(xv, w_l[k * C + c], al);
        au = fmaf(xv, w_u[k * C + c], au);
        aw = fmaf(xv, w_lin[k * C + c], aw);
    }
    size_t o = (size_t)row * C + c;
    g_xm_l[o] = al;
    g_xm_u[o] = au;
    out[o] = aw * EPSF;
}

// ---------------------------------------------------------------------------
// Kernel B: per-node attention scalars. One warp per node.
// ---------------------------------------------------------------------------
__global__ void scalars_kernel(const float* __restrict__ a_l,
                               const float* __restrict__ a_u) {
    int warp = (blockIdx.x * blockDim.x + threadIdx.x) >> 5;
    int lane = threadIdx.x & 31;
    if (warp >= NN) return;
    size_t base = (size_t)warp * C;

    float xl0 = g_xm_l[base + lane];
    float xl1 = g_xm_l[base + 32 + lane];
    float xu0 = g_xm_u[base + lane];
    float xu1 = g_xm_u[base + 32 + lane];

    float ssl = xl0 * a_l[lane]      + xl1 * a_l[lane + 32];
    float stl = xl0 * a_l[lane + 64] + xl1 * a_l[lane + 96];
    float ssu = xu0 * a_u[lane]      + xu1 * a_u[lane + 32];
    float stu = xu0 * a_u[lane + 64] + xu1 * a_u[lane + 96];

#pragma unroll
    for (int off = 16; off > 0; off >>= 1) {
        ssl += __shfl_xor_sync(0xFFFFFFFFu, ssl, off);
        stl += __shfl_xor_sync(0xFFFFFFFFu, stl, off);
        ssu += __shfl_xor_sync(0xFFFFFFFFu, ssu, off);
        stu += __shfl_xor_sync(0xFFFFFFFFu, stu, off);
    }
    if (lane == 0) {
        g_ss[warp]          = ssl;
        g_ss[NN + warp]     = stl;
        g_ss[2 * NN + warp] = ssu;
        g_ss[3 * NN + warp] = stu;
    }
}

// ---------------------------------------------------------------------------
// Kernel C: edge scatter v2.
// 16 threads/edge. Lane 0 of each 16-group loads indices + scalars and
// computes alpha once; broadcast via shfl(width=16). Each lane: one float4
// gather + ONE red.global.add.v4.f32 (4x fewer RED wavefronts than scalar).
// ---------------------------------------------------------------------------
template <int LOWER>
__global__ void edge_kernel(const int* __restrict__ idx,
                            const float* __restrict__ vals,
                            float* __restrict__ out) {
    int t = blockIdx.x * blockDim.x + threadIdx.x;
    int e = t >> 4;
    if (e >= EE) return;
    int lane16 = t & 15;
    int part = lane16 * 4;

    const float* xm    = LOWER ? g_xm_l : g_xm_u;
    const float* s_src = LOWER ? g_ss          : g_ss + 2 * NN;
    const float* s_tgt = LOWER ? g_ss + NN     : g_ss + 3 * NN;

    int i = 0, j = 0;
    float alpha = 0.f;
    if (lane16 == 0) {
        i = idx[e];
        j = idx[EE + e];
        float s = s_src[j] + s_tgt[i];
        float el = (s > 0.f) ? s : expm1f(s);
        alpha = el * vals[e];
    }
    i     = __shfl_sync(0xFFFFFFFFu, i, 0, 16);
    j     = __shfl_sync(0xFFFFFFFFu, j, 0, 16);
    alpha = __shfl_sync(0xFFFFFFFFu, alpha, 0, 16);

    float4 m = *reinterpret_cast<const float4*>(xm + (size_t)j * C + part);
    float rx = alpha * m.x, ry = alpha * m.y, rz = alpha * m.z, rw = alpha * m.w;
    float* p = out + (size_t)i * C + part;
    asm volatile("red.global.add.v4.f32 [%0], {%1, %2, %3, %4};"
                 :: "l"(p), "f"(rx), "f"(ry), "f"(rz), "f"(rw)
                 : "memory");
}

// ---------------------------------------------------------------------------
// Kernel D: in-place ReLU on d_out.
// ---------------------------------------------------------------------------
__global__ void relu_kernel(float* __restrict__ out) {
    int t = blockIdx.x * blockDim.x + threadIdx.x;
    if (t >= NN * C / 4) return;
    float4* p = reinterpret_cast<float4*>(out) + t;
    float4 v = *p;
    v.x = fmaxf(v.x, 0.f);
    v.y = fmaxf(v.y, 0.f);
    v.z = fmaxf(v.z, 0.f);
    v.w = fmaxf(v.w, 0.f);
    *p = v;
}

// ---------------------------------------------------------------------------
extern "C" void kernel_launch(void* const* d_in, const int* in_sizes, int n_in,
                              void* d_out, int out_size) {
    const float* x      = (const float*)d_in[0];
    const int*   l_idx  = (const int*)d_in[1];
    const float* l_vals = (const float*)d_in[2];
    const int*   u_idx  = (const int*)d_in[3];
    const float* u_vals = (const float*)d_in[4];
    const float* w_l    = (const float*)d_in[5];
    const float* a_l    = (const float*)d_in[6];
    const float* w_u    = (const float*)d_in[7];
    const float* a_u    = (const float*)d_in[8];
    const float* w_lin  = (const float*)d_in[9];
    float* out = (float*)d_out;

    // A: GEMMs (+ w_x -> d_out overwrite)
    gemm3_kernel<<<(NN + 3) / 4, 256>>>(x, w_l, w_u, w_lin, out);

    // B: attention scalars (warp per node, 8 warps/block)
    scalars_kernel<<<(NN + 7) / 8, 256>>>(a_l, a_u);

    // C: edge scatters (16 threads/edge)
    int eblocks = (EE * 16) / 256;  // exact
    edge_kernel<1><<<eblocks, 256>>>(l_idx, l_vals, out);
    edge_kernel<0><<<eblocks, 256>>>(u_idx, u_vals, out);

    // D: ReLU in place
    relu_kernel<<<(NN * C / 4 + 255) / 256, 256>>>(out);
}

// round 8
// speedup vs baseline: 2.0658x; 1.3301x over previous
#include <cuda_runtime.h>
#include <math.h>

#define NN 50000
#define EE 800000
#define C 64
#define EPSF 1.000001f

// Scratch (device globals: no allocation allowed anywhere).
__device__ __align__(16) float g_xm_l[NN * C];
__device__ __align__(16) float g_xm_u[NN * C];
__device__ float g_ss[4 * NN];   // [s_src_l | s_tgt_l | s_src_u | s_tgt_u]

// ---------------------------------------------------------------------------
// Kernel A: three fused GEMMs + attention-scalar epilogue (old kernel B).
// Block = 256 threads = 4 slots x 64 cols; each slot handles 2 rows.
// Per row: xm_l, xm_u -> scratch; (x @ w_lin)*EPS -> d_out;
//          s_src/s_tgt scalars for both branches -> g_ss.
// ---------------------------------------------------------------------------
__global__ void gemm3_fused_kernel(const float* __restrict__ x,
                                   const float* __restrict__ w_l,
                                   const float* __restrict__ w_u,
                                   const float* __restrict__ w_lin,
                                   const float* __restrict__ a_l,
                                   const float* __restrict__ a_u,
                                   float* __restrict__ out) {
    __shared__ float xs[8][C];
    __shared__ float sred[4][2][8];   // [slot][warp-half][8 partials]

    int slot = threadIdx.x >> 6;       // 0..3
    int c    = threadIdx.x & 63;       // 0..63
    int half = c >> 5;                 // which warp within the slot
    int lane = c & 31;
    int row0 = blockIdx.x * 8 + slot * 2;   // rows row0, row0+1

    // Stage 8 rows of x into shared (2 elements per thread).
#pragma unroll
    for (int v = 0; v < 2; v++) {
        int idx = threadIdx.x + v * 256;    // 0..511
        int r = idx >> 6, cc = idx & 63;
        int grow = blockIdx.x * 8 + r;
        xs[r][cc] = (grow < NN) ? x[(size_t)grow * C + cc] : 0.f;
    }
    __syncthreads();

    float al0 = 0.f, al1 = 0.f, au0 = 0.f, au1 = 0.f, aw0 = 0.f, aw1 = 0.f;
#pragma unroll
    for (int k = 0; k < C; k++) {
        float wl = w_l[k * C + c];
        float wu = w_u[k * C + c];
        float ww = w_lin[k * C + c];
        float x0 = xs[slot * 2][k];
        float x1 = xs[slot * 2 + 1][k];
        al0 = fmaf(x0, wl, al0);  al1 = fmaf(x1, wl, al1);
        au0 = fmaf(x0, wu, au0);  au1 = fmaf(x1, wu, au1);
        aw0 = fmaf(x0, ww, aw0);  aw1 = fmaf(x1, ww, aw1);
    }

    bool r0ok = (row0 < NN), r1ok = (row0 + 1 < NN);
    if (r0ok) {
        size_t o = (size_t)row0 * C + c;
        g_xm_l[o] = al0; g_xm_u[o] = au0; out[o] = aw0 * EPSF;
    }
    if (r1ok) {
        size_t o = (size_t)(row0 + 1) * C + c;
        g_xm_l[o] = al1; g_xm_u[o] = au1; out[o] = aw1 * EPSF;
    }

    // Attention scalars: reduce across the 64 cols of each row.
    float alc0 = a_l[c], alc1 = a_l[64 + c];
    float auc0 = a_u[c], auc1 = a_u[64 + c];
    float p[8];
    p[0] = al0 * alc0; p[1] = al0 * alc1;   // row0: ssl, stl
    p[2] = au0 * auc0; p[3] = au0 * auc1;   // row0: ssu, stu
    p[4] = al1 * alc0; p[5] = al1 * alc1;   // row1
    p[6] = au1 * auc0; p[7] = au1 * auc1;
#pragma unroll
    for (int off = 16; off > 0; off >>= 1) {
#pragma unroll
        for (int v = 0; v < 8; v++)
            p[v] += __shfl_xor_sync(0xFFFFFFFFu, p[v], off);
    }
    if (lane == 0) {
#pragma unroll
        for (int v = 0; v < 8; v++) sred[slot][half][v] = p[v];
    }
    __syncthreads();
    if (c == 0) {
#pragma unroll
        for (int v = 0; v < 8; v++) {
            float s = sred[slot][0][v] + sred[slot][1][v];
            int row = row0 + (v >> 2);
            if (row < NN) {
                int which = v & 3;   // 0=ssl 1=stl 2=ssu 3=stu
                // layout: [s_src_l | s_tgt_l | s_src_u | s_tgt_u]
                int base = (which == 0) ? 0 : (which == 1) ? NN
                          : (which == 2) ? 2 * NN : 3 * NN;
                g_ss[base + row] = s;
            }
        }
    }
}

// ---------------------------------------------------------------------------
// Kernel C: fused edge scatter (lower + upper per edge).
// 16 threads/edge; lane 0 computes both alphas, broadcast via shfl.
// Two independent gather+RED chains per thread -> 2x MLP.
// ---------------------------------------------------------------------------
__global__ void edge_fused_kernel(const int* __restrict__ l_idx,
                                  const float* __restrict__ l_vals,
                                  const int* __restrict__ u_idx,
                                  const float* __restrict__ u_vals,
                                  float* __restrict__ out) {
    int t = blockIdx.x * blockDim.x + threadIdx.x;
    int e = t >> 4;
    if (e >= EE) return;
    int lane16 = t & 15;
    int part = lane16 * 4;

    int il = 0, jl = 0, iu = 0, ju = 0;
    float al = 0.f, au = 0.f;
    if (lane16 == 0) {
        il = l_idx[e];  jl = l_idx[EE + e];
        iu = u_idx[e];  ju = u_idx[EE + e];
        float sl = g_ss[jl]          + g_ss[NN + il];
        float su = g_ss[2 * NN + ju] + g_ss[3 * NN + iu];
        sl = (sl > 0.f) ? sl : expm1f(sl);
        su = (su > 0.f) ? su : expm1f(su);
        al = sl * l_vals[e];
        au = su * u_vals[e];
    }
    il = __shfl_sync(0xFFFFFFFFu, il, 0, 16);
    jl = __shfl_sync(0xFFFFFFFFu, jl, 0, 16);
    iu = __shfl_sync(0xFFFFFFFFu, iu, 0, 16);
    ju = __shfl_sync(0xFFFFFFFFu, ju, 0, 16);
    al = __shfl_sync(0xFFFFFFFFu, al, 0, 16);
    au = __shfl_sync(0xFFFFFFFFu, au, 0, 16);

    float4 ml = *reinterpret_cast<const float4*>(g_xm_l + (size_t)jl * C + part);
    float4 mu = *reinterpret_cast<const float4*>(g_xm_u + (size_t)ju * C + part);

    float* pl = out + (size_t)il * C + part;
    asm volatile("red.global.add.v4.f32 [%0], {%1, %2, %3, %4};"
                 :: "l"(pl), "f"(al * ml.x), "f"(al * ml.y),
                    "f"(al * ml.z), "f"(al * ml.w) : "memory");
    float* pu = out + (size_t)iu * C + part;
    asm volatile("red.global.add.v4.f32 [%0], {%1, %2, %3, %4};"
                 :: "l"(pu), "f"(au * mu.x), "f"(au * mu.y),
                    "f"(au * mu.z), "f"(au * mu.w) : "memory");
}

// ---------------------------------------------------------------------------
// Kernel D: in-place ReLU on d_out.
// ---------------------------------------------------------------------------
__global__ void relu_kernel(float* __restrict__ out) {
    int t = blockIdx.x * blockDim.x + threadIdx.x;
    if (t >= NN * C / 4) return;
    float4* p = reinterpret_cast<float4*>(out) + t;
    float4 v = *p;
    v.x = fmaxf(v.x, 0.f);
    v.y = fmaxf(v.y, 0.f);
    v.z = fmaxf(v.z, 0.f);
    v.w = fmaxf(v.w, 0.f);
    *p = v;
}

// ---------------------------------------------------------------------------
extern "C" void kernel_launch(void* const* d_in, const int* in_sizes, int n_in,
                              void* d_out, int out_size) {
    const float* x      = (const float*)d_in[0];
    const int*   l_idx  = (const int*)d_in[1];
    const float* l_vals = (const float*)d_in[2];
    const int*   u_idx  = (const int*)d_in[3];
    const float* u_vals = (const float*)d_in[4];
    const float* w_l    = (const float*)d_in[5];
    const float* a_l    = (const float*)d_in[6];
    const float* w_u    = (const float*)d_in[7];
    const float* a_u    = (const float*)d_in[8];
    const float* w_lin  = (const float*)d_in[9];
    float* out = (float*)d_out;

    // A: GEMMs + scalars epilogue (8 rows/block)
    gemm3_fused_kernel<<<(NN + 7) / 8, 256>>>(x, w_l, w_u, w_lin, a_l, a_u, out);

    // C: fused edge scatter (16 threads/edge, both branches)
    int eblocks = (EE * 16) / 256;  // exact: 50000
    edge_fused_kernel<<<eblocks, 256>>>(l_idx, l_vals, u_idx, u_vals, out);

    // D: ReLU in place
    relu_kernel<<<(NN * C / 4 + 255) / 256, 256>>>(out);
}

// round 10
// speedup vs baseline: 2.3001x; 1.1134x over previous
#include <cuda_runtime.h>
#include <math.h>

#define NN 50000
#define EE 800000
#define C 64
#define EPSF 1.000001f

// Scratch (device globals: no allocation allowed anywhere).
__device__ __align__(16) float g_xm_l[NN * C];
__device__ __align__(16) float g_xm_u[NN * C];
__device__ float g_ss[4 * NN];   // [s_src_l | s_tgt_l | s_src_u | s_tgt_u]

// ---------------------------------------------------------------------------
// Kernel A: three fused GEMMs + attention-scalar epilogue.
// Block = 256 threads, tile 64 rows x 64 cols, thread tile 4x4.
// tid = ct + 16*rt : ct in [0,16) -> cols 4*ct..4*ct+3 ; rt in [0,16) -> rows 4*rt..
// Per k: 3x LDG.128 (w) + 4x LDS -> 48 FMA.
// ---------------------------------------------------------------------------
__global__ __launch_bounds__(256) void gemm3_v3_kernel(
        const float* __restrict__ x,
        const float* __restrict__ w_l,
        const float* __restrict__ w_u,
        const float* __restrict__ w_lin,
        const float* __restrict__ a_l,
        const float* __restrict__ a_u,
        float* __restrict__ out) {
    __shared__ float xs[64][64];

    int tid = threadIdx.x;
    int ct = tid & 15;          // col-thread
    int rt = tid >> 4;          // row-thread
    int c0 = ct * 4;
    int rowbase = blockIdx.x * 64 + rt * 4;

    // Stage 64 rows of x (zero-padded past NN).
#pragma unroll
    for (int v = 0; v < 4; v++) {
        int f = tid + v * 256;          // float4 index in [0,1024)
        int r = f >> 4, c4 = f & 15;
        int grow = blockIdx.x * 64 + r;
        float4 val = make_float4(0.f, 0.f, 0.f, 0.f);
        if (grow < NN)
            val = *reinterpret_cast<const float4*>(x + (size_t)grow * C + c4 * 4);
        *reinterpret_cast<float4*>(&xs[r][c4 * 4]) = val;
    }
    __syncthreads();

    float4 al[4], au[4], aw[4];
#pragma unroll
    for (int rr = 0; rr < 4; rr++) {
        al[rr] = make_float4(0.f, 0.f, 0.f, 0.f);
        au[rr] = make_float4(0.f, 0.f, 0.f, 0.f);
        aw[rr] = make_float4(0.f, 0.f, 0.f, 0.f);
    }

#pragma unroll 8
    for (int k = 0; k < C; k++) {
        float4 wl = *reinterpret_cast<const float4*>(w_l   + k * C + c0);
        float4 wu = *reinterpret_cast<const float4*>(w_u   + k * C + c0);
        float4 ww = *reinterpret_cast<const float4*>(w_lin + k * C + c0);
#pragma unroll
        for (int rr = 0; rr < 4; rr++) {
            float xv = xs[rt * 4 + rr][k];
            al[rr].x = fmaf(xv, wl.x, al[rr].x);
            al[rr].y = fmaf(xv, wl.y, al[rr].y);
            al[rr].z = fmaf(xv, wl.z, al[rr].z);
            al[rr].w = fmaf(xv, wl.w, al[rr].w);
            au[rr].x = fmaf(xv, wu.x, au[rr].x);
            au[rr].y = fmaf(xv, wu.y, au[rr].y);
            au[rr].z = fmaf(xv, wu.z, au[rr].z);
            au[rr].w = fmaf(xv, wu.w, au[rr].w);
            aw[rr].x = fmaf(xv, ww.x, aw[rr].x);
            aw[rr].y = fmaf(xv, ww.y, aw[rr].y);
            aw[rr].z = fmaf(xv, ww.z, aw[rr].z);
            aw[rr].w = fmaf(xv, ww.w, aw[rr].w);
        }
    }

    // Write xm_l / xm_u / out (float4, 16B-aligned).
#pragma unroll
    for (int rr = 0; rr < 4; rr++) {
        int row = rowbase + rr;
        if (row < NN) {
            size_t o = (size_t)row * C + c0;
            *reinterpret_cast<float4*>(g_xm_l + o) = al[rr];
            *reinterpret_cast<float4*>(g_xm_u + o) = au[rr];
            float4 w4 = aw[rr];
            w4.x *= EPSF; w4.y *= EPSF; w4.z *= EPSF; w4.w *= EPSF;
            *reinterpret_cast<float4*>(out + o) = w4;
        }
    }

    // Attention scalars: per row dot with a[:64] and a[64:], both branches.
    float4 Al0 = *reinterpret_cast<const float4*>(a_l + c0);
    float4 Al1 = *reinterpret_cast<const float4*>(a_l + 64 + c0);
    float4 Au0 = *reinterpret_cast<const float4*>(a_u + c0);
    float4 Au1 = *reinterpret_cast<const float4*>(a_u + 64 + c0);

#pragma unroll
    for (int rr = 0; rr < 4; rr++) {
        float ssl = al[rr].x * Al0.x + al[rr].y * Al0.y + al[rr].z * Al0.z + al[rr].w * Al0.w;
        float stl = al[rr].x * Al1.x + al[rr].y * Al1.y + al[rr].z * Al1.z + al[rr].w * Al1.w;
        float ssu = au[rr].x * Au0.x + au[rr].y * Au0.y + au[rr].z * Au0.z + au[rr].w * Au0.w;
        float stu = au[rr].x * Au1.x + au[rr].y * Au1.y + au[rr].z * Au1.z + au[rr].w * Au1.w;
#pragma unroll
        for (int off = 8; off > 0; off >>= 1) {
            ssl += __shfl_xor_sync(0xFFFFFFFFu, ssl, off, 16);
            stl += __shfl_xor_sync(0xFFFFFFFFu, stl, off, 16);
            ssu += __shfl_xor_sync(0xFFFFFFFFu, ssu, off, 16);
            stu += __shfl_xor_sync(0xFFFFFFFFu, stu, off, 16);
        }
        int row = rowbase + rr;
        if (ct == 0 && row < NN) {
            g_ss[row]          = ssl;
            g_ss[NN + row]     = stl;
            g_ss[2 * NN + row] = ssu;
            g_ss[3 * NN + row] = stu;
        }
    }
}

// ---------------------------------------------------------------------------
// Kernel C: fused edge scatter (lower + upper per edge).
// 16 threads/edge; lane 0 computes both alphas, broadcast via shfl.
// ---------------------------------------------------------------------------
__global__ void edge_fused_kernel(const int* __restrict__ l_idx,
                                  const float* __restrict__ l_vals,
                                  const int* __restrict__ u_idx,
                                  const float* __restrict__ u_vals,
                                  float* __restrict__ out) {
    int t = blockIdx.x * blockDim.x + threadIdx.x;
    int e = t >> 4;
    if (e >= EE) return;
    int lane16 = t & 15;
    int part = lane16 * 4;

    int il = 0, jl = 0, iu = 0, ju = 0;
    float al = 0.f, au = 0.f;
    if (lane16 == 0) {
        il = l_idx[e];  jl = l_idx[EE + e];
        iu = u_idx[e];  ju = u_idx[EE + e];
        float sl = g_ss[jl]          + g_ss[NN + il];
        float su = g_ss[2 * NN + ju] + g_ss[3 * NN + iu];
        sl = (sl > 0.f) ? sl : expm1f(sl);
        su = (su > 0.f) ? su : expm1f(su);
        al = sl * l_vals[e];
        au = su * u_vals[e];
    }
    il = __shfl_sync(0xFFFFFFFFu, il, 0, 16);
    jl = __shfl_sync(0xFFFFFFFFu, jl, 0, 16);
    iu = __shfl_sync(0xFFFFFFFFu, iu, 0, 16);
    ju = __shfl_sync(0xFFFFFFFFu, ju, 0, 16);
    al = __shfl_sync(0xFFFFFFFFu, al, 0, 16);
    au = __shfl_sync(0xFFFFFFFFu, au, 0, 16);

    float4 ml = *reinterpret_cast<const float4*>(g_xm_l + (size_t)jl * C + part);
    float4 mu = *reinterpret_cast<const float4*>(g_xm_u + (size_t)ju * C + part);

    float* pl = out + (size_t)il * C + part;
    asm volatile("red.global.add.v4.f32 [%0], {%1, %2, %3, %4};"
                 :: "l"(pl), "f"(al * ml.x), "f"(al * ml.y),
                    "f"(al * ml.z), "f"(al * ml.w) : "memory");
    float* pu = out + (size_t)iu * C + part;
    asm volatile("red.global.add.v4.f32 [%0], {%1, %2, %3, %4};"
                 :: "l"(pu), "f"(au * mu.x), "f"(au * mu.y),
                    "f"(au * mu.z), "f"(au * mu.w) : "memory");
}

// ---------------------------------------------------------------------------
// Kernel D: in-place ReLU on d_out.
// ---------------------------------------------------------------------------
__global__ void relu_kernel(float* __restrict__ out) {
    int t = blockIdx.x * blockDim.x + threadIdx.x;
    if (t >= NN * C / 4) return;
    float4* p = reinterpret_cast<float4*>(out) + t;
    float4 v = *p;
    v.x = fmaxf(v.x, 0.f);
    v.y = fmaxf(v.y, 0.f);
    v.z = fmaxf(v.z, 0.f);
    v.w = fmaxf(v.w, 0.f);
    *p = v;
}

// ---------------------------------------------------------------------------
extern "C" void kernel_launch(void* const* d_in, const int* in_sizes, int n_in,
                              void* d_out, int out_size) {
    const float* x      = (const float*)d_in[0];
    const int*   l_idx  = (const int*)d_in[1];
    const float* l_vals = (const float*)d_in[2];
    const int*   u_idx  = (const int*)d_in[3];
    const float* u_vals = (const float*)d_in[4];
    const float* w_l    = (const float*)d_in[5];
    const float* a_l    = (const float*)d_in[6];
    const float* w_u    = (const float*)d_in[7];
    const float* a_u    = (const float*)d_in[8];
    const float* w_lin  = (const float*)d_in[9];
    float* out = (float*)d_out;

    // A: GEMMs + scalars epilogue (64 rows/block, 4x4 thread tiles)
    gemm3_v3_kernel<<<(NN + 63) / 64, 256>>>(x, w_l, w_u, w_lin, a_l, a_u, out);

    // C: fused edge scatter (16 threads/edge, both branches)
    int eblocks = (EE * 16) / 256;  // exact: 50000
    edge_fused_kernel<<<eblocks, 256>>>(l_idx, l_vals, u_idx, u_vals, out);

    // D: ReLU in place
    relu_kernel<<<(NN * C / 4 + 255) / 256, 256>>>(out);
}